// round 12
// baseline (speedup 1.0000x reference)
#include <cuda_runtime.h>
#include <cstdint>

#define Bb 64
#define Tt 1024
#define Ii 64
#define Hh 512
#define G3 1536
#define MM (Bb*Tt)      // 65536 rows

// ---------------- scratch (device globals: allocation-free) ----------------
__device__ float g_xg[(size_t)MM * G3];   // input-side gates, TIME-MAJOR rows (t*B+b)
__device__ float g_y [(size_t)MM * Hh];   // hidden history, TIME-MAJOR rows (t*B+b)

struct __align__(128) PadFlag { unsigned v; unsigned pad[31]; };
__device__ PadFlag g_flag[4][32];         // per (group, producer-block) monotonic step flags

// ---------------- helpers ----------------
__device__ __forceinline__ float to_tf32(float x) {
    unsigned u;
    asm("cvt.rna.tf32.f32 %0, %1;" : "=r"(u) : "f"(x));
    return __uint_as_float(u);
}

__device__ __forceinline__ void mma_tf32(float* c, const unsigned* a, unsigned b0, unsigned b1) {
    asm("mma.sync.aligned.m16n8k8.row.col.f32.tf32.tf32.f32 "
        "{%0,%1,%2,%3},{%4,%5,%6,%7},{%8,%9},{%0,%1,%2,%3};"
        : "+f"(c[0]), "+f"(c[1]), "+f"(c[2]), "+f"(c[3])
        : "r"(a[0]), "r"(a[1]), "r"(a[2]), "r"(a[3]), "r"(b0), "r"(b1));
}

__device__ __forceinline__ unsigned smem_u32(const void* p) {
    return (unsigned)__cvta_generic_to_shared(p);
}

// hard spin — no nanosleep
__device__ __forceinline__ void waitflag(const unsigned* p, unsigned tgt) {
    unsigned v;
    do {
        asm volatile("ld.global.acquire.gpu.b32 %0, [%1];" : "=r"(v) : "l"(p) : "memory");
    } while ((int)(v - tgt) < 0);
}

// ---------------- generic tf32 GEMM: C[m][n] = sum_k A[m][k]*W[n][k] + bias[n] ----
// mode: output row remap. 0: ro=m  1: m=(b*T+t) -> ro=t*B+b   2: m=(t*B+b) -> ro=b*T+t
__global__ __launch_bounds__(256) void gemm_tf32(
    const float* __restrict__ A, const float* __restrict__ W,
    const float* __restrict__ bias, float* __restrict__ C,
    int M, int N, int K, int mode)
{
    __shared__ float As[128][20];
    __shared__ float Ws[64][20];
    const int tid  = threadIdx.x;
    const int warp = tid >> 5, lane = tid & 31;
    const int gID  = lane >> 2, tig = lane & 3;
    const int wm   = warp >> 1, wn = warp & 1;
    const int m0   = blockIdx.y * 128, n0 = blockIdx.x * 64;

    float acc[2][4][4];
    #pragma unroll
    for (int i = 0; i < 2; i++)
        #pragma unroll
        for (int j = 0; j < 4; j++)
            #pragma unroll
            for (int q = 0; q < 4; q++) acc[i][j][q] = 0.f;

    for (int k0 = 0; k0 < K; k0 += 16) {
        #pragma unroll
        for (int i = 0; i < 2; i++) {
            int idx = tid + i * 256;
            int r = idx >> 2, cb = idx & 3;
            float4 v = *(const float4*)(A + (size_t)(m0 + r) * K + k0 + cb * 4);
            *(float4*)(&As[r][cb * 4]) =
                make_float4(to_tf32(v.x), to_tf32(v.y), to_tf32(v.z), to_tf32(v.w));
        }
        {
            int r = tid >> 2, cb = tid & 3;
            float4 v = *(const float4*)(W + (size_t)(n0 + r) * K + k0 + cb * 4);
            *(float4*)(&Ws[r][cb * 4]) =
                make_float4(to_tf32(v.x), to_tf32(v.y), to_tf32(v.z), to_tf32(v.w));
        }
        __syncthreads();
        #pragma unroll
        for (int s = 0; s < 2; s++) {
            const int kk = s * 8;
            unsigned a[2][4];
            #pragma unroll
            for (int mt = 0; mt < 2; mt++) {
                int r = wm * 32 + mt * 16 + gID;
                a[mt][0] = __float_as_uint(As[r][kk + tig]);
                a[mt][1] = __float_as_uint(As[r + 8][kk + tig]);
                a[mt][2] = __float_as_uint(As[r][kk + tig + 4]);
                a[mt][3] = __float_as_uint(As[r + 8][kk + tig + 4]);
            }
            #pragma unroll
            for (int nt = 0; nt < 4; nt++) {
                int n = wn * 32 + nt * 8 + gID;
                unsigned b0 = __float_as_uint(Ws[n][kk + tig]);
                unsigned b1 = __float_as_uint(Ws[n][kk + tig + 4]);
                #pragma unroll
                for (int mt = 0; mt < 2; mt++)
                    mma_tf32(acc[mt][nt], a[mt], b0, b1);
            }
        }
        __syncthreads();
    }
    #pragma unroll
    for (int mt = 0; mt < 2; mt++) {
        #pragma unroll
        for (int rr = 0; rr < 2; rr++) {
            int r = m0 + wm * 32 + mt * 16 + rr * 8 + gID;
            int ro = (mode == 0) ? r
                   : (mode == 1) ? ((r & (Tt - 1)) * Bb + (r >> 10))
                                 : ((r & (Bb - 1)) * Tt + (r >> 6));
            #pragma unroll
            for (int nt = 0; nt < 4; nt++) {
                int c = n0 + wn * 32 + nt * 8 + tig * 2;
                C[(size_t)ro * N + c]     = acc[mt][nt][rr * 2]     + bias[c];
                C[(size_t)ro * N + c + 1] = acc[mt][nt][rr * 2 + 1] + bias[c + 1];
            }
        }
    }
}

// ---------------- persistent recurrent kernel (dataflow, parallel-poll) ----
// 128 blocks: bid&3 = batch group (16 batches), bid>>2 = hidden block hb (16 units).
// Warp w consumes chunks 4w..4w+3. Lanes 0-3 poll the 4 producer flags in
// PARALLEL; then all 4 chunks' cp.asyncs issue at once (single wait_group 0).
// The block's own chunk is read from smem (own[]), skipping global entirely.
#define PS 49
#define STF (8*4*16*20)          // stage floats
#define REC_SMEM ((STF + 16*20 + 8*16*PS + 48) * 4)

__global__ __launch_bounds__(256, 1) void gru_rec(
    const float* __restrict__ xg, const float* __restrict__ whh,
    const float* __restrict__ bhh, float* __restrict__ y)
{
    extern __shared__ float sm[];
    float* stage = sm;                      // [warp][chunk][row16][20]
    float* own   = stage + STF;             // [16][20]
    float* part  = own + 16 * 20;           // [warp][16][PS]
    float* b_s   = part + 8 * 16 * PS;      // [48]
    __shared__ unsigned s_base;

    const int bid  = blockIdx.x;
    const int grp  = bid & 3;
    const int hb   = bid >> 2;
    const int tid  = threadIdx.x;
    const int warp = tid >> 5, lane = tid & 31;
    const int gID  = lane >> 2, tig = lane & 3;
    const int bb   = tid >> 4, uu = tid & 15;
    const int bglob = grp * 16;
    const int k0w  = warp * 64;

    // one-time: W_hh fragments into registers (tf32-rounded)
    unsigned breg[8][6][2];
    #pragma unroll
    for (int nt = 0; nt < 6; nt++) {
        int r = nt * 8 + gID;                          // 0..47
        int grow = (r >> 4) * Hh + hb * 16 + (r & 15);
        const float* wrow = whh + (size_t)grow * Hh;
        #pragma unroll
        for (int ks = 0; ks < 8; ks++) {
            int k = k0w + ks * 8 + tig;
            breg[ks][nt][0] = __float_as_uint(to_tf32(wrow[k]));
            breg[ks][nt][1] = __float_as_uint(to_tf32(wrow[k + 4]));
        }
    }
    if (tid < 48) b_s[tid] = bhh[(tid >> 4) * Hh + hb * 16 + (tid & 15)];
    if (tid == 0) s_base = *(volatile unsigned*)&g_flag[grp][hb].v;  // equal across blocks
    __syncthreads();
    const unsigned base = s_base;

    const int b  = bglob + bb;
    const int ug = hb * 16 + uu;
    float hprev = 0.f;                                  // tf32-rounded h_{t-1}(b,ug)

    for (int t = 0; t < Tt; t++) {
        // prefetch input-side gates (consumed in gate phase)
        const size_t xb = ((size_t)t * Bb + b) * (size_t)G3;
        float xr = __ldg(xg + xb + ug);
        float xz = __ldg(xg + xb + Hh + ug);
        float xn = __ldg(xg + xb + 2 * Hh + ug);

        float acc[6][4];
        #pragma unroll
        for (int nt = 0; nt < 6; nt++) { acc[nt][0]=acc[nt][1]=acc[nt][2]=acc[nt][3]=0.f; }

        if (t > 0) {
            const float* ybase = y + ((size_t)(t - 1) * Bb + bglob) * Hh;
            const unsigned tgt = base + (unsigned)t;
            const int c0 = warp * 4;

            // PARALLEL poll: lanes 0-3 each spin on one producer flag
            if (lane < 4) {
                int j = c0 + lane;
                if (j != hb) waitflag(&g_flag[grp][j].v, tgt);
            }
            __syncwarp();

            // issue ALL 4 chunks' loads back-to-back (skip own chunk)
            #pragma unroll
            for (int c = 0; c < 4; c++) {
                int j = c0 + c;
                if (j != hb) {
                    #pragma unroll
                    for (int i = 0; i < 2; i++) {
                        int idx = lane + 32 * i;
                        int row = idx >> 2, seg = idx & 3;
                        const float* src = ybase + (size_t)row * Hh + j * 16 + seg * 4;
                        float* dst = stage + (((warp * 4 + c) * 16 + row) * 20 + seg * 4);
                        asm volatile("cp.async.cg.shared.global [%0], [%1], 16;"
                                     :: "r"(smem_u32(dst)), "l"(src) : "memory");
                    }
                }
            }
            asm volatile("cp.async.commit_group;\n\tcp.async.wait_group 0;" ::: "memory");
            __syncwarp();

            // all 4 chunks' MMAs
            #pragma unroll
            for (int c = 0; c < 4; c++) {
                const float* st = (c0 + c == hb) ? own
                                : stage + ((warp * 4 + c) * 16 * 20);
                #pragma unroll
                for (int s = 0; s < 2; s++) {
                    const int kk = s * 8;
                    unsigned a[4];
                    a[0] = __float_as_uint(st[gID * 20 + kk + tig]);
                    a[1] = __float_as_uint(st[(gID + 8) * 20 + kk + tig]);
                    a[2] = __float_as_uint(st[gID * 20 + kk + tig + 4]);
                    a[3] = __float_as_uint(st[(gID + 8) * 20 + kk + tig + 4]);
                    #pragma unroll
                    for (int nt = 0; nt < 6; nt++)
                        mma_tf32(acc[nt], a, breg[c * 2 + s][nt][0], breg[c * 2 + s][nt][1]);
                }
            }
        }

        // partials to smem
        float* pw = part + warp * 16 * PS;
        #pragma unroll
        for (int nt = 0; nt < 6; nt++) {
            int c = nt * 8 + tig * 2;
            pw[gID * PS + c]           = acc[nt][0];
            pw[gID * PS + c + 1]       = acc[nt][1];
            pw[(gID + 8) * PS + c]     = acc[nt][2];
            pw[(gID + 8) * PS + c + 1] = acc[nt][3];
        }
        __syncthreads();

        // gate phase: fold 8-way k-reduction; one (batch, unit) per thread
        float hr = b_s[uu], hz = b_s[16 + uu], hn = b_s[32 + uu];
        #pragma unroll
        for (int w = 0; w < 8; w++) {
            const float* p = part + (w * 16 + bb) * PS;
            hr += p[uu]; hz += p[16 + uu]; hn += p[32 + uu];
        }
        float ar = xr + hr; ar = fminf(fmaxf(ar, -30.f), 30.f);
        float az = xz + hz; az = fminf(fmaxf(az, -30.f), 30.f);
        float r = __fdividef(1.f, 1.f + __expf(-ar));
        float z = __fdividef(1.f, 1.f + __expf(-az));
        float an = xn + r * hn; an = fminf(fmaxf(an, -15.f), 15.f);
        float n = 1.f - __fdividef(2.f, __expf(2.f * an) + 1.f);
        float hnew = (1.f - z) * n + z * hprev;
        float hro = to_tf32(hnew);
        hprev = hro;
        y[((size_t)t * Bb + b) * Hh + ug] = hro;
        own[bb * 20 + uu] = hro;                         // smem copy for own-chunk consumers

        // publish: block sync (orders y stores, protects part/own/stage), then
        // one release store (coop-groups grid-sync pattern)
        __syncthreads();
        if (tid == 0) {
            unsigned nv = base + (unsigned)t + 1u;
            asm volatile("st.global.release.gpu.b32 [%0], %1;"
                         :: "l"(&g_flag[grp][hb].v), "r"(nv) : "memory");
        }
    }
}

// ---------------- launch ----------------
extern "C" void kernel_launch(void* const* d_in, const int* in_sizes, int n_in,
                              void* d_out, int out_size)
{
    const float* x    = (const float*)d_in[0];
    const float* wih0 = (const float*)d_in[1];
    const float* whh0 = (const float*)d_in[2];
    const float* bih0 = (const float*)d_in[3];
    const float* bhh0 = (const float*)d_in[4];
    const float* wih1 = (const float*)d_in[5];
    const float* whh1 = (const float*)d_in[6];
    const float* bih1 = (const float*)d_in[7];
    const float* bhh1 = (const float*)d_in[8];
    const float* fcw  = (const float*)d_in[9];
    const float* fcb  = (const float*)d_in[10];
    float* out = (float*)d_out;

    float *xgp = 0, *yp = 0;
    cudaGetSymbolAddress((void**)&xgp, g_xg);
    cudaGetSymbolAddress((void**)&yp,  g_y);

    cudaFuncSetAttribute(gru_rec, cudaFuncAttributeMaxDynamicSharedMemorySize, REC_SMEM);

    // xg0 (time-major out): rows of x are b*T+t -> write t*B+b   (mode 1)
    gemm_tf32<<<dim3(G3 / 64, MM / 128), 256>>>(x, wih0, bih0, xgp, MM, G3, Ii, 1);
    // layer 0 recurrence -> y (time-major)
    gru_rec<<<128, 256, REC_SMEM>>>(xgp, whh0, bhh0, yp);
    // xg1: y0 rows already t*B+b -> same order out                (mode 0)
    gemm_tf32<<<dim3(G3 / 64, MM / 128), 256>>>(yp, wih1, bih1, xgp, MM, G3, Hh, 0);
    // layer 1 recurrence -> y
    gru_rec<<<128, 256, REC_SMEM>>>(xgp, whh1, bhh1, yp);
    // FC: y1 rows t*B+b -> out rows b*T+t                         (mode 2)
    gemm_tf32<<<dim3(Ii / 64, MM / 128), 256>>>(yp, fcw, fcb, out, MM, Ii, Hh, 2);
}